// round 17
// baseline (speedup 1.0000x reference)
#include <cuda_runtime.h>

// Problem: x (2,128,512,512) f32.
//   edge = sum_o |conv(sum_c x, sobel_o)|  (channel-independent)
//   out  = maxpool2x2(edge) broadcast to (2,128,256,256)
//
// 2-phase software pipeline, NO warp specialization. 256 blocks x 512
// threads; block owns pooled row py of BOTH batches:
//   for b in {0,1}:
//     read(b):  channel-half sum of rows {2py,2py+1} (__ldcs), combine,
//               publish to g_sum, post monotonic flag
//     halo(b):  short spin on neighbors (all blocks post ~simultaneously)
//     sobel(b): 4x sobel + abs-sum + 2x2 maxpool -> rowbuf
//     store(b): 8x 32B st.global.L2::evict_last per thread, FIRE-AND-FORGET
//               -> b=0 stores drain through idle issue slots + L2 during
//               b=1's 20us read stream (stores hit L2-resident lines: no
//               DRAM demand). Only b=1's stores (~7us) are exposed.
// Store tail is STG-issue-bound (~1 STG.128/cyc/SM), not BW-bound — hiding
// it needs idle issue slots, which the read phase has in abundance.

#define S_SPATIAL   (512 * 512)
#define S_SPATIAL4  (S_SPATIAL / 4)   // 65536
#define NCH         128
#define NB          2
#define NBLK        256               // one per pooled row
#define NT          512

__device__ float g_sum[NB * S_SPATIAL];       // 2 MB scratch
__device__ unsigned int g_flag[NB * 256];     // monotonic, per (b,py)
__device__ unsigned int g_seq[256];           // per-block launch counter

__device__ __forceinline__ float edge_at(const float* r0, const float* r1,
                                         const float* r2, int x0) {
    float a = r0[x0],  bb = r0[x0+1], c = r0[x0+2];
    float d = r1[x0],                  f = r1[x0+2];
    float g = r2[x0],  h = r2[x0+1],  i = r2[x0+2];
    // XLA conv = cross-correlation (no kernel flip)
    float e0 = -a + c - 2.f*d + 2.f*f - g + i;
    float e1 =  a + 2.f*bb + c - g - 2.f*h - i;
    float e2 =  2.f*a + bb + d - f - h - 2.f*i;
    float e3 = -bb - 2.f*c + d - f + 2.f*g + h;
    return fabsf(e0) + fabsf(e1) + fabsf(e2) + fabsf(e3);
}

// 32-byte store with L2 evict_last (sm_103 requires .v8.b32/.v4.b64 form)
__device__ __forceinline__ void st_evict_last_32B(void* p, ulonglong4 v) {
    asm volatile("st.global.L2::evict_last.v4.b64 [%0], {%1,%2,%3,%4};"
                 :: "l"(p), "l"(v.x), "l"(v.y), "l"(v.z), "l"(v.w) : "memory");
}

#define SROW_W 520   // 514 used (x = -1 .. 512), padded

__global__ void __launch_bounds__(NT) k_fused(const float4* __restrict__ x,
                                              float4* __restrict__ out) {
    __shared__ float srow[4][SROW_W];        // rows 2py-1..2py+2, x shifted +1
    __shared__ float4 spart[256];            // channel-half partials
    __shared__ __align__(32) float rowbuf[NB][256];
    __shared__ unsigned int s_k;

    int py  = blockIdx.x;                    // 0..255
    int tid = threadIdx.x;

    if (tid == 0) s_k = atomicAdd(&g_seq[py], 1u) + 1u;
    __syncthreads();
    unsigned int k = s_k;

#pragma unroll
    for (int b = 0; b < NB; b++) {
        // ---- read(b): channel-half sum of rows {2py, 2py+1} ----
        int j    = tid & 255;                // f4 slot: row = 2py+(j>>7), col = j&127
        int half = tid >> 8;                 // 0: ch 0-63, 1: ch 64-127
        int sp   = py * 256 + j;             // f4 index within batch plane
        const float4* p = x + ((size_t)b * NCH + (size_t)half * 64) * S_SPATIAL4 + sp;
        float4 acc = make_float4(0.f, 0.f, 0.f, 0.f);
#pragma unroll 8
        for (int c = 0; c < 64; c++) {
            float4 v = __ldcs(p + (size_t)c * S_SPATIAL4);  // evict-first
            acc.x += v.x; acc.y += v.y; acc.z += v.z; acc.w += v.w;
        }
        if (half) spart[j] = acc;
        __syncthreads();
        if (!half) {
            float4 o2 = spart[j];
            acc.x += o2.x; acc.y += o2.y; acc.z += o2.z; acc.w += o2.w;
            ((float4*)g_sum)[(b << 16) + sp] = acc;         // for neighbors
            int r  = j >> 7;
            int f4 = j & 127;
            float* dst = &srow[1 + r][1 + 4 * f4];
            dst[0] = acc.x; dst[1] = acc.y; dst[2] = acc.z; dst[3] = acc.w;
        }
        __threadfence();                     // release g_sum
        __syncthreads();                     // all block stores done
        if (tid == 0) atomicAdd(&g_flag[(b << 8) | py], 1u);

        // ---- halo(b): wait neighbors (short — all post ~simultaneously) ----
        if (tid < 2) {                       // tid 0: py-1, tid 1: py+1
            int npy = py + (tid ? 1 : -1);
            if (npy >= 0 && npy < 256) {
                volatile unsigned int* f =
                    (volatile unsigned int*)&g_flag[(b << 8) | npy];
                while (*f < k) __nanosleep(100);
            }
            __threadfence();                 // acquire
        }
        __syncthreads();

        if (tid < 256) {
            int hr = tid >> 7;               // 0: top halo, 1: bottom halo
            int f4 = tid & 127;
            int y  = hr ? (2 * py + 2) : (2 * py - 1);
            float4 v = make_float4(0.f, 0.f, 0.f, 0.f);
            if (y >= 0 && y < 512)
                v = __ldcg((const float4*)(g_sum + b * S_SPATIAL + y * 512) + f4);
            float* dst = &srow[hr ? 3 : 0][1 + 4 * f4];
            dst[0] = v.x; dst[1] = v.y; dst[2] = v.z; dst[3] = v.w;
        }
        if (tid < 8) {                       // halo cols x=-1, x=512 are zero
            int r = tid >> 1;
            srow[r][(tid & 1) ? 513 : 0] = 0.f;
        }
        __syncthreads();

        // ---- sobel(b): 4x sobel + abs-sum + 2x2 maxpool ----
        if (tid < 256) {
            int xb = 2 * tid;
            const float *r0 = srow[0], *r1 = srow[1], *r2 = srow[2], *r3 = srow[3];
            rowbuf[b][tid] = fmaxf(
                fmaxf(edge_at(r0, r1, r2, xb), edge_at(r0, r1, r2, xb + 1)),
                fmaxf(edge_at(r1, r2, r3, xb), edge_at(r1, r2, r3, xb + 1)));
        }
        __syncthreads();

        // ---- store(b): 4096 x 32B chunks / 512 threads = 8 per thread ----
        // Fire-and-forget: next loop iteration's reads begin immediately;
        // these stores drain behind that read stream.
        {
            int chunk0 = tid;                // chunk = csub*32 + i32
            ulonglong4 v = ((const ulonglong4*)rowbuf[b])[chunk0 & 31];
            // all 8 chunks for this thread share i32 = tid&31? No:
            // chunk = tid + i*512 -> i32 = chunk & 31 = tid & 31 (512 % 32 == 0)
            int i32 = tid & 31;
            char* obase = (char*)out + ((size_t)b * NCH * 256) * 1024
                        + (size_t)py * 1024 + i32 * 32;
#pragma unroll
            for (int i = 0; i < 8; i++) {
                int csub = (tid + i * NT) >> 5;      // channel 0..127
                st_evict_last_32B(obase + (size_t)csub * 256 * 1024, v);
            }
        }
        // no barrier here: rowbuf value already captured in register v, and
        // the next phase's first touch of shared state is after syncthreads.
    }
}

extern "C" void kernel_launch(void* const* d_in, const int* in_sizes, int n_in,
                              void* d_out, int out_size) {
    const float4* x = (const float4*)d_in[0];
    float4* out = (float4*)d_out;

    k_fused<<<NBLK, NT>>>(x, out);
}